// round 4
// baseline (speedup 1.0000x reference)
#include <cuda_runtime.h>
#include <math.h>

#define NN 20000
#define EE 320000
#define DD 128
#define HH 8
#define PP 16
#define GG 64
#define WIDTHF (5.0f/63.0f)
#define LN_EPS 1e-5f

// ---------------- scratch (device globals; no allocation allowed) ----------
__device__ float g_q[(size_t)EE*DD];      // layernormed edge features
__device__ float g_v[(size_t)EE*DD];      // v_vec
__device__ float g_logit[(size_t)EE*HH];  // logits, then exp-numerators
__device__ float g_C[EE];                 // cosine cutoff per edge
__device__ float g_qvec[(size_t)NN*DD];   // node-level q
__device__ float g_h2[(size_t)NN*DD];     // aggregated he
__device__ int   g_mmax[(size_t)NN*HH];   // segment max (monotone-int encoded)
__device__ float g_ssum[(size_t)NN*HH];   // segment sum of a*C

// monotone float<->int encoding for atomicMax on signed int
__device__ __forceinline__ int fenc(float f) {
    int i = __float_as_int(f);
    return (i < 0) ? (i ^ 0x7fffffff) : i;
}
__device__ __forceinline__ float fdec(int i) {
    return __int_as_float((i < 0) ? (i ^ 0x7fffffff) : i);
}

__device__ __forceinline__ float tf32r(float x) {
    unsigned int o;
    asm("cvt.rna.tf32.f32 %0, %1;" : "=r"(o) : "f"(x));
    return __uint_as_float(o);
}

// ---------------- init segment buffers ------------------------------------
__global__ void k_init() {
    int t = blockIdx.x * blockDim.x + threadIdx.x;
    if (t < NN * DD) g_h2[t] = 0.0f;
    if (t < NN * HH) {
        g_mmax[t] = fenc(__int_as_float(0xff800000)); // -inf
        g_ssum[t] = 0.0f;
    }
}

// ---------------- K1: distances, RBF filter GEMM, cutoff, q = LN(W*h1[dst]+t)
__global__ __launch_bounds__(256) void k_edge_filter(
    const float* __restrict__ pos, const float* __restrict__ h1,
    const float* __restrict__ t_in, const float* __restrict__ fw,
    const float* __restrict__ fb, const float* __restrict__ lng,
    const float* __restrict__ lnb, const int* __restrict__ src,
    const int* __restrict__ dst, float* __restrict__ outW)
{
    extern __shared__ float sm[];
    float* s_fw = sm;                 // [GG][DD] 32KB
    float* s_f2 = sm + GG * DD;       // [64][GG] 16KB
    __shared__ float s_r[64], s_C[64];
    __shared__ int s_dst[64];

    const int tid = threadIdx.x;
    const int base = blockIdx.x * 64;

    for (int i = tid; i < GG * DD / 4; i += 256)
        ((float4*)s_fw)[i] = ((const float4*)fw)[i];

    if (tid < 64) {
        int e = base + tid;
        int sI = src[e], dI = dst[e];
        float dx = pos[dI * 3 + 0] - pos[sI * 3 + 0];
        float dy = pos[dI * 3 + 1] - pos[sI * 3 + 1];
        float dz = pos[dI * 3 + 2] - pos[sI * 3 + 2];
        float r = sqrtf(dx * dx + dy * dy + dz * dz);
        float C = (r < 5.0f) ? 0.5f * (cospif(r * 0.2f) + 1.0f) : 0.0f;
        s_r[tid] = r; s_C[tid] = C; s_dst[tid] = dI;
        g_C[e] = C;
    }
    __syncthreads();

    const float alpha = -0.5f / (WIDTHF * WIDTHF);
    for (int idx = tid; idx < 64 * GG; idx += 256) {
        int e = idx >> 6, g = idx & 63;
        float diff = s_r[e] - (float)g * WIDTHF;
        float f2 = (fabsf(diff) < 8.0f * WIDTHF)
                       ? 2.0f * __expf(alpha * diff * diff) - 1.0f
                       : -1.0f;
        s_f2[e * GG + g] = f2;
    }
    __syncthreads();

    const int tx = tid & 31, ty = tid >> 5;
    float4 fbv = ((const float4*)fb)[tx];
    float4 acc[8];
#pragma unroll
    for (int i = 0; i < 8; i++) acc[i] = fbv;

#pragma unroll 4
    for (int g4 = 0; g4 < GG / 4; g4++) {
        float4 b0 = *(const float4*)&s_fw[(4 * g4 + 0) * DD + tx * 4];
        float4 b1 = *(const float4*)&s_fw[(4 * g4 + 1) * DD + tx * 4];
        float4 b2 = *(const float4*)&s_fw[(4 * g4 + 2) * DD + tx * 4];
        float4 b3 = *(const float4*)&s_fw[(4 * g4 + 3) * DD + tx * 4];
#pragma unroll
        for (int i = 0; i < 8; i++) {
            float4 a = *(const float4*)&s_f2[(ty * 8 + i) * GG + 4 * g4];
            acc[i].x += a.x * b0.x + a.y * b1.x + a.z * b2.x + a.w * b3.x;
            acc[i].y += a.x * b0.y + a.y * b1.y + a.z * b2.y + a.w * b3.y;
            acc[i].z += a.x * b0.z + a.y * b1.z + a.z * b2.z + a.w * b3.z;
            acc[i].w += a.x * b0.w + a.y * b1.w + a.z * b2.w + a.w * b3.w;
        }
    }

    float4 gv = ((const float4*)lng)[tx];
    float4 bv = ((const float4*)lnb)[tx];
#pragma unroll
    for (int i = 0; i < 8; i++) {
        int el = ty * 8 + i;
        int e = base + el;
        float C = s_C[el];
        float4 w = acc[i];
        w.x *= C; w.y *= C; w.z *= C; w.w *= C;
        ((float4*)outW)[(size_t)e * 32 + tx] = w;

        int dI = s_dst[el];
        float4 hv = ((const float4*)h1)[(size_t)dI * 32 + tx];
        float4 tv = ((const float4*)t_in)[(size_t)e * 32 + tx];
        float4 q;
        q.x = w.x * hv.x + tv.x;
        q.y = w.y * hv.y + tv.y;
        q.z = w.z * hv.z + tv.z;
        q.w = w.w * hv.w + tv.w;

        float ps = q.x + q.y + q.z + q.w;
        float pss = q.x * q.x + q.y * q.y + q.z * q.z + q.w * q.w;
#pragma unroll
        for (int o = 16; o; o >>= 1) {
            ps += __shfl_xor_sync(0xffffffffu, ps, o);
            pss += __shfl_xor_sync(0xffffffffu, pss, o);
        }
        float mu = ps * (1.0f / 128.0f);
        float var = pss * (1.0f / 128.0f) - mu * mu;
        float rstd = rsqrtf(var + LN_EPS);
        q.x = (q.x - mu) * rstd * gv.x + bv.x;
        q.y = (q.y - mu) * rstd * gv.y + bv.y;
        q.z = (q.z - mu) * rstd * gv.z + bv.z;
        q.w = (q.w - mu) * rstd * gv.w + bv.w;
        ((float4*)g_q)[(size_t)e * 32 + tx] = q;
    }
}

// SIMT GEMM inner: out[64 rows x 128] = s_A[64x128] @ s_B[128x128]
__device__ __forceinline__ void gemm_tile(const float* s_A, const float* s_B,
                                          float4 acc[8], int tx, int ty)
{
#pragma unroll 4
    for (int k4 = 0; k4 < DD / 4; k4++) {
        float4 b0 = *(const float4*)&s_B[(4 * k4 + 0) * DD + tx * 4];
        float4 b1 = *(const float4*)&s_B[(4 * k4 + 1) * DD + tx * 4];
        float4 b2 = *(const float4*)&s_B[(4 * k4 + 2) * DD + tx * 4];
        float4 b3 = *(const float4*)&s_B[(4 * k4 + 3) * DD + tx * 4];
#pragma unroll
        for (int i = 0; i < 8; i++) {
            float4 a = *(const float4*)&s_A[(ty * 8 + i) * DD + 4 * k4];
            acc[i].x += a.x * b0.x + a.y * b1.x + a.z * b2.x + a.w * b3.x;
            acc[i].y += a.x * b0.y + a.y * b1.y + a.z * b2.y + a.w * b3.y;
            acc[i].z += a.x * b0.z + a.y * b1.z + a.z * b2.z + a.w * b3.z;
            acc[i].w += a.x * b0.w + a.y * b1.w + a.z * b2.w + a.w * b3.w;
        }
    }
}

// ---------------- K2: q_vec = q[q_id] @ Wq  (node-level) -------------------
__global__ __launch_bounds__(256) void k_qvec(const float* __restrict__ Wq,
                                              const int* __restrict__ q_id)
{
    extern __shared__ float sm[];
    float* s_A = sm;
    float* s_B = sm + 64 * DD;
    const int tid = threadIdx.x;
    const int base = blockIdx.x * 64;

    for (int i = tid; i < DD * DD / 4; i += 256)
        ((float4*)s_B)[i] = ((const float4*)Wq)[i];
    for (int i = tid; i < 64 * DD / 4; i += 256) {
        int row = i >> 5, c4 = i & 31;
        int gr = base + row;
        float4 vv = make_float4(0.f, 0.f, 0.f, 0.f);
        if (gr < NN) {
            int ar = q_id[gr];
            vv = ((const float4*)g_q)[(size_t)ar * 32 + c4];
        }
        ((float4*)s_A)[i] = vv;
    }
    __syncthreads();

    const int tx = tid & 31, ty = tid >> 5;
    float4 acc[8];
#pragma unroll
    for (int i = 0; i < 8; i++) acc[i] = make_float4(0.f, 0.f, 0.f, 0.f);
    gemm_tile(s_A, s_B, acc, tx, ty);
#pragma unroll
    for (int i = 0; i < 8; i++) {
        int gr = base + ty * 8 + i;
        if (gr < NN) ((float4*)g_qvec)[(size_t)gr * 32 + tx] = acc[i];
    }
}

// ---------------- K3 (tensor): fused k|v = q @ [Wk|Wv] ---------------------
// Block: 512 threads (16 warps, warpM 0..3 x warpG 0..3).
// Tile M=128 edges, N=256 fused (k half = cols 0..127, v half = 128..255).
// SMEM holds A and B pre-permuted into mma fragment order:
//   A: [ks][wm][mt][lane] float4   (16*4*2*32*4 = 16384 floats, 64KB)
//   B: [ks][wg][g ][lane] float4   (16*4*4*32*4 = 32768 floats, 128KB)
// -> mainloop: 2 LDS.128 (A) + 4 LDS.128 (B) + 16 mma per k-step.

__device__ __forceinline__ int afrag_idx(int row, int k) {
    int ks = k >> 3, wm = row >> 5, row5 = row & 31;
    int lane = ((row5 & 7) << 2) | (k & 3);
    int j = row5 >> 3;                 // which of 4 row-slots
    int mt = j >> 1, rh = j & 1, pk = (k >> 2) & 1;
    return (((ks * 4 + wm) * 2 + mt) * 32 + lane) * 4 + pk * 2 + rh;
}
__device__ __forceinline__ int bfrag_idx(int k, int n) {
    int ks = k >> 3, wg = n >> 6, n64 = n & 63;
    int lane = ((n64 & 7) << 2) | (k & 3);
    int nt = n64 >> 3;
    return (((ks * 4 + wg) * 4 + (nt >> 1)) * 32 + lane) * 4 +
           (nt & 1) * 2 + ((k >> 2) & 1);
}

__device__ __forceinline__ void mma_tf32(float c[4], const unsigned a[4],
                                         const unsigned b[2])
{
    asm volatile(
        "mma.sync.aligned.m16n8k8.row.col.f32.tf32.tf32.f32 "
        "{%0,%1,%2,%3}, {%4,%5,%6,%7}, {%8,%9}, {%0,%1,%2,%3};"
        : "+f"(c[0]), "+f"(c[1]), "+f"(c[2]), "+f"(c[3])
        : "r"(a[0]), "r"(a[1]), "r"(a[2]), "r"(a[3]), "r"(b[0]), "r"(b[1]));
}

__global__ __launch_bounds__(512) void k_kv(const float* __restrict__ Wk,
                                            const float* __restrict__ Wv,
                                            const int* __restrict__ src)
{
    extern __shared__ float sm[];
    float* s_qf = sm;              // 16384 floats (A fragments)
    float* s_Bf = sm + 16384;      // 32768 floats (B fragments)
    __shared__ int s_src[128];

    const int tid = threadIdx.x;
    const int lane = tid & 31;
    const int wid = tid >> 5;
    const int warpM = wid & 3;
    const int warpG = wid >> 2;
    const int base = blockIdx.x * 128;

    // ---- stage A (q tile) into fragment order, tf32-rounded ----
    for (int i = tid; i < 128 * 32; i += 512) {
        int row = i >> 5, c4 = i & 31;
        float4 v = ((const float4*)g_q)[(size_t)(base + row) * 32 + c4];
        float vals[4] = {tf32r(v.x), tf32r(v.y), tf32r(v.z), tf32r(v.w)};
        int kb = c4 * 4;
#pragma unroll
        for (int u = 0; u < 4; u++)
            s_qf[afrag_idx(row, kb + u)] = vals[u];
    }
    if (tid < 128) s_src[tid] = src[base + tid];
    // ---- stage B = [Wk | Wv] into fragment order ----
    for (int i = tid; i < 128 * 32; i += 512) {
        int k = i >> 5, c4 = i & 31;
        float4 v = ((const float4*)Wk)[i];
        float vals[4] = {tf32r(v.x), tf32r(v.y), tf32r(v.z), tf32r(v.w)};
        int nb = c4 * 4;
#pragma unroll
        for (int u = 0; u < 4; u++)
            s_Bf[bfrag_idx(k, nb + u)] = vals[u];
    }
    for (int i = tid; i < 128 * 32; i += 512) {
        int k = i >> 5, c4 = i & 31;
        float4 v = ((const float4*)Wv)[i];
        float vals[4] = {tf32r(v.x), tf32r(v.y), tf32r(v.z), tf32r(v.w)};
        int nb = 128 + c4 * 4;
#pragma unroll
        for (int u = 0; u < 4; u++)
            s_Bf[bfrag_idx(k, nb + u)] = vals[u];
    }
    __syncthreads();

    const int rA = warpM * 32 + (lane >> 2);
    const int kA_unused = 0; (void)kA_unused;

    float c[2][8][4];
#pragma unroll
    for (int mt = 0; mt < 2; mt++)
#pragma unroll
        for (int nt = 0; nt < 8; nt++)
#pragma unroll
            for (int j = 0; j < 4; j++) c[mt][nt][j] = 0.0f;

    const float4* fA = (const float4*)s_qf;
    const float4* fB = (const float4*)s_Bf;

    // ---- fused mainloop ----
#pragma unroll
    for (int ks = 0; ks < 16; ks++) {
        float4 fa0 = fA[((ks * 4 + warpM) * 2 + 0) * 32 + lane];
        float4 fa1 = fA[((ks * 4 + warpM) * 2 + 1) * 32 + lane];
        unsigned a[2][4] = {
            {__float_as_uint(fa0.x), __float_as_uint(fa0.y),
             __float_as_uint(fa0.z), __float_as_uint(fa0.w)},
            {__float_as_uint(fa1.x), __float_as_uint(fa1.y),
             __float_as_uint(fa1.z), __float_as_uint(fa1.w)}};
        float4 fb[4];
#pragma unroll
        for (int g = 0; g < 4; g++)
            fb[g] = fB[((ks * 4 + warpG) * 4 + g) * 32 + lane];
        unsigned b[8][2];
#pragma unroll
        for (int g = 0; g < 4; g++) {
            b[2 * g + 0][0] = __float_as_uint(fb[g].x);
            b[2 * g + 0][1] = __float_as_uint(fb[g].y);
            b[2 * g + 1][0] = __float_as_uint(fb[g].z);
            b[2 * g + 1][1] = __float_as_uint(fb[g].w);
        }
#pragma unroll
        for (int mt = 0; mt < 2; mt++)
#pragma unroll
            for (int nt = 0; nt < 8; nt++)
                mma_tf32(c[mt][nt], a[mt], b[nt]);
    }

    if (warpG < 2) {
        // ---- epilogue (k half): logits via per-head dot with q_vec[src] ----
        float ph[2][2][4];
#pragma unroll
        for (int mt = 0; mt < 2; mt++)
#pragma unroll
            for (int hf = 0; hf < 2; hf++)
#pragma unroll
                for (int h = 0; h < 4; h++) ph[mt][hf][h] = 0.0f;

        const int col0base = warpG * 64 + 2 * (lane & 3);
#pragma unroll
        for (int mt = 0; mt < 2; mt++) {
#pragma unroll
            for (int hf = 0; hf < 2; hf++) {
                int r = rA + mt * 16 + hf * 8;
                int sI = s_src[r];
                const float* qv = &g_qvec[(size_t)sI * DD];
#pragma unroll
                for (int nt = 0; nt < 8; nt++) {
                    float2 q2 = *(const float2*)&qv[col0base + nt * 8];
                    ph[mt][hf][nt >> 1] +=
                        c[mt][nt][2 * hf] * q2.x + c[mt][nt][2 * hf + 1] * q2.y;
                }
            }
        }
#pragma unroll
        for (int mt = 0; mt < 2; mt++)
#pragma unroll
            for (int hf = 0; hf < 2; hf++)
#pragma unroll
                for (int h = 0; h < 4; h++) {
                    float v = ph[mt][hf][h];
                    v += __shfl_xor_sync(0xffffffffu, v, 1);
                    v += __shfl_xor_sync(0xffffffffu, v, 2);
                    ph[mt][hf][h] = v;
                }
        int hl = lane & 3;
        int head = warpG * 4 + hl;
#pragma unroll
        for (int mt = 0; mt < 2; mt++)
#pragma unroll
            for (int hf = 0; hf < 2; hf++) {
                int r = rA + mt * 16 + hf * 8;
                int e = base + r;
                int sI = s_src[r];
                float logit = ph[mt][hf][hl] * 0.25f;
                g_logit[(size_t)e * HH + head] = logit;
                atomicMax(&g_mmax[(size_t)sI * HH + head], fenc(logit));
            }
    } else {
        // ---- epilogue (v half): store v fragments ----
        const int col0 = (warpG - 2) * 64 + 2 * (lane & 3);
#pragma unroll
        for (int mt = 0; mt < 2; mt++) {
            int r = rA + mt * 16;
#pragma unroll
            for (int nt = 0; nt < 8; nt++) {
                int cc = col0 + nt * 8;
                *(float2*)&g_v[(size_t)(base + r) * DD + cc] =
                    make_float2(c[mt][nt][0], c[mt][nt][1]);
                *(float2*)&g_v[(size_t)(base + r + 8) * DD + cc] =
                    make_float2(c[mt][nt][2], c[mt][nt][3]);
            }
        }
    }
}

// ---------------- K4: a = exp(logit - m[src]) * C ; segment-sum ------------
__global__ void k_soft(const int* __restrict__ src) {
    int t = blockIdx.x * blockDim.x + threadIdx.x;
    if (t >= EE * HH) return;
    int e = t >> 3, h = t & 7;
    int sI = src[e];
    float m = fdec(g_mmax[(size_t)sI * HH + h]);
    float a = __expf(g_logit[t] - m) * g_C[e];
    g_logit[t] = a;
    atomicAdd(&g_ssum[(size_t)sI * HH + h], a);
}

// ---------------- K5: he = v * att ; vector red to h2[src] -----------------
__global__ __launch_bounds__(256) void k_scatter(const int* __restrict__ src) {
    const int tid = threadIdx.x;
    const int tx = tid & 31, wid = tid >> 5;
    int e = blockIdx.x * 8 + wid;
    int sI = __ldg(&src[e]);
    int h = tx >> 2;
    float att = g_logit[(size_t)e * HH + h] / g_ssum[(size_t)sI * HH + h];
    float4 v = ((const float4*)g_v)[(size_t)e * 32 + tx];
    float* dp = &g_h2[(size_t)sI * DD + tx * 4];
    asm volatile("red.global.add.v4.f32 [%0], {%1, %2, %3, %4};"
                 :: "l"(dp), "f"(v.x * att), "f"(v.y * att),
                    "f"(v.z * att), "f"(v.w * att)
                 : "memory");
}

// ---------------- K6: m_agg = h2 @ Wo --------------------------------------
__global__ __launch_bounds__(256) void k_out(const float* __restrict__ Wo,
                                             float* __restrict__ outM)
{
    extern __shared__ float sm[];
    float* s_A = sm;
    float* s_B = sm + 64 * DD;
    const int tid = threadIdx.x;
    const int base = blockIdx.x * 64;

    for (int i = tid; i < DD * DD / 4; i += 256)
        ((float4*)s_B)[i] = ((const float4*)Wo)[i];
    for (int i = tid; i < 64 * DD / 4; i += 256) {
        int row = i >> 5, c4 = i & 31;
        int gr = base + row;
        float4 vv = make_float4(0.f, 0.f, 0.f, 0.f);
        if (gr < NN) vv = ((const float4*)g_h2)[(size_t)gr * 32 + c4];
        ((float4*)s_A)[i] = vv;
    }
    __syncthreads();

    const int tx = tid & 31, ty = tid >> 5;
    float4 acc[8];
#pragma unroll
    for (int i = 0; i < 8; i++) acc[i] = make_float4(0.f, 0.f, 0.f, 0.f);
    gemm_tile(s_A, s_B, acc, tx, ty);
#pragma unroll
    for (int i = 0; i < 8; i++) {
        int gr = base + ty * 8 + i;
        if (gr < NN) ((float4*)outM)[(size_t)gr * 32 + tx] = acc[i];
    }
}

// ---------------------------------------------------------------------------
extern "C" void kernel_launch(void* const* d_in, const int* in_sizes, int n_in,
                              void* d_out, int out_size)
{
    const float* pos  = (const float*)d_in[0];
    const float* h1   = (const float*)d_in[1];
    const float* t_in = (const float*)d_in[2];
    const float* fw   = (const float*)d_in[3];
    const float* fb   = (const float*)d_in[4];
    const float* lng  = (const float*)d_in[5];
    const float* lnb  = (const float*)d_in[6];
    const float* Wq   = (const float*)d_in[7];
    const float* Wk   = (const float*)d_in[8];
    const float* Wv   = (const float*)d_in[9];
    const float* Wo   = (const float*)d_in[10];
    const int* src    = (const int*)d_in[11];
    const int* dst    = (const int*)d_in[12];
    const int* q_id   = (const int*)d_in[13];

    float* outM = (float*)d_out;                       // [N, D]
    float* outW = outM + (size_t)NN * DD;              // [E, D]

    const int smem_filter = (GG * DD + 64 * GG) * sizeof(float);       // 48KB
    const int smem_gemm   = (64 * DD + DD * DD) * sizeof(float);       // 96KB
    const int smem_kv     = (16384 + 32768) * sizeof(float);           // 192KB
    cudaFuncSetAttribute(k_edge_filter, cudaFuncAttributeMaxDynamicSharedMemorySize, smem_filter);
    cudaFuncSetAttribute(k_qvec, cudaFuncAttributeMaxDynamicSharedMemorySize, smem_gemm);
    cudaFuncSetAttribute(k_kv,   cudaFuncAttributeMaxDynamicSharedMemorySize, smem_kv);
    cudaFuncSetAttribute(k_out,  cudaFuncAttributeMaxDynamicSharedMemorySize, smem_gemm);

    k_init<<<(NN * DD + 255) / 256, 256>>>();
    k_edge_filter<<<EE / 64, 256, smem_filter>>>(pos, h1, t_in, fw, fb, lng, lnb,
                                                 src, dst, outW);
    k_qvec<<<(NN + 63) / 64, 256, smem_gemm>>>(Wq, q_id);
    k_kv<<<EE / 128, 512, smem_kv>>>(Wk, Wv, src);
    k_soft<<<(EE * HH + 255) / 256, 256>>>(src);
    k_scatter<<<EE / 8, 256>>>(src);
    k_out<<<(NN + 63) / 64, 256, smem_gemm>>>(Wo, outM);
}